// round 2
// baseline (speedup 1.0000x reference)
#include <cuda_runtime.h>

#define DD 128
#define MAXN 50000
#define MAXE 800000

// ---------------- device scratch (static: no allocations allowed) ----------------
__device__ float g_mean[(size_t)MAXN * DD];   // per-layer aggregated mean
__device__ float g_ha[(size_t)MAXN * DD];     // layer outputs ping
__device__ float g_hb[(size_t)MAXN * DD];     // layer outputs pong
__device__ float g_invdeg[MAXN];
__device__ int   g_degi[MAXN];
__device__ int   g_rowstart[MAXN + 1];
__device__ int   g_cursor[MAXN];
__device__ int   g_csr[MAXE];

// ---------------- CSR construction (once per launch; edges are layer-invariant) ----------------
__global__ void zero_counts(int n) {
    int i = blockIdx.x * blockDim.x + threadIdx.x;
    if (i < n) { g_degi[i] = 0; g_cursor[i] = 0; }
}

// edge_index is int32 (JAX x64 disabled downcasts int64 -> int32)
__global__ void count_deg(const int* __restrict__ ei, int E) {
    int e = blockIdx.x * blockDim.x + threadIdx.x;
    if (e < E) atomicAdd(&g_degi[ei[E + e]], 1);
}

// exclusive scan of g_degi into g_rowstart, single block of 1024 threads
__global__ void scan_kernel(int n) {
    __shared__ int warp_sums[32];
    __shared__ int s_carry;
    int t = threadIdx.x;
    int lane = t & 31, w = t >> 5;
    if (t == 0) { g_rowstart[0] = 0; s_carry = 0; }
    __syncthreads();
    for (int base = 0; base < n; base += 1024) {
        int i = base + t;
        int v = (i < n) ? g_degi[i] : 0;
        int x = v;
        #pragma unroll
        for (int off = 1; off < 32; off <<= 1) {
            int y = __shfl_up_sync(0xFFFFFFFFu, x, off);
            if (lane >= off) x += y;
        }
        if (lane == 31) warp_sums[w] = x;
        __syncthreads();
        if (w == 0) {
            int s = warp_sums[lane];
            #pragma unroll
            for (int off = 1; off < 32; off <<= 1) {
                int y = __shfl_up_sync(0xFFFFFFFFu, s, off);
                if (lane >= off) s += y;
            }
            warp_sums[lane] = s;
        }
        __syncthreads();
        int incl = x + (w > 0 ? warp_sums[w - 1] : 0) + s_carry;
        if (i < n) g_rowstart[i + 1] = incl;
        __syncthreads();
        if (t == 1023) s_carry = incl;
        __syncthreads();
    }
}

__global__ void invdeg_kernel(int n) {
    int i = blockIdx.x * blockDim.x + threadIdx.x;
    if (i < n) {
        int dg = g_degi[i];
        g_invdeg[i] = 1.0f / (float)(dg > 0 ? dg : 1);
    }
}

__global__ void fill_csr(const int* __restrict__ ei, int E) {
    int e = blockIdx.x * blockDim.x + threadIdx.x;
    if (e < E) {
        int s = ei[e];
        int d = ei[E + e];
        int p = atomicAdd(&g_cursor[d], 1);
        g_csr[g_rowstart[d] + p] = s;
    }
}

// ---------------- aggregation: warp per node, gather-only, no atomics ----------------
__global__ void aggregate_kernel(const float* __restrict__ hin, int n) {
    int gw = (blockIdx.x * blockDim.x + threadIdx.x) >> 5;
    int lane = threadIdx.x & 31;
    if (gw >= n) return;
    int s0 = g_rowstart[gw], s1 = g_rowstart[gw + 1];
    float ax = 0.f, ay = 0.f, az = 0.f, aw = 0.f;
    int i = s0;
    for (; i + 4 <= s1; i += 4) {
        int e0 = g_csr[i], e1 = g_csr[i + 1], e2 = g_csr[i + 2], e3 = g_csr[i + 3];
        float4 v0 = *(const float4*)(hin + (size_t)e0 * DD + lane * 4);
        float4 v1 = *(const float4*)(hin + (size_t)e1 * DD + lane * 4);
        float4 v2 = *(const float4*)(hin + (size_t)e2 * DD + lane * 4);
        float4 v3 = *(const float4*)(hin + (size_t)e3 * DD + lane * 4);
        ax += v0.x + v1.x + v2.x + v3.x;
        ay += v0.y + v1.y + v2.y + v3.y;
        az += v0.z + v1.z + v2.z + v3.z;
        aw += v0.w + v1.w + v2.w + v3.w;
    }
    for (; i < s1; i++) {
        int e0 = g_csr[i];
        float4 v = *(const float4*)(hin + (size_t)e0 * DD + lane * 4);
        ax += v.x; ay += v.y; az += v.z; aw += v.w;
    }
    float inv = g_invdeg[gw];
    float4 r;
    r.x = ax * inv; r.y = ay * inv; r.z = az * inv; r.w = aw * inv;
    *(float4*)(g_mean + (size_t)gw * DD + lane * 4) = r;
}

// ---------------- fused dual GEMM: out = mean @ Wl + h @ Wr + b (+ReLU) ----------------
// Block tile: 128 rows x 64 cols. 256 threads, thread tile 4 rows x 8 cols.
// Cols per thread split as {c0+cg*4..+3} and {c0+32+cg*4..+3} => W smem loads conflict-free.
#define SMEM_FLOATS (2 * 128 * 132 + 2 * 128 * 64)
#define SMEM_BYTES  (SMEM_FLOATS * 4)

template <bool RELU>
__global__ __launch_bounds__(256) void combine_kernel(
    const float* __restrict__ mean, const float* __restrict__ h,
    const float* __restrict__ wl, const float* __restrict__ wr,
    const float* __restrict__ bias, float* __restrict__ out, int n)
{
    extern __shared__ float sm[];
    float* sM  = sm;                 // [128][132] padded
    float* sH  = sM + 128 * 132;     // [128][132]
    float* sWl = sH + 128 * 132;     // [128][64]
    float* sWr = sWl + 128 * 64;     // [128][64]

    int tid = threadIdx.x;
    int row0 = blockIdx.x * 128;
    int c0 = blockIdx.y * 64;

    // stage A tiles (mean, h): 128 rows x 32 float4
    for (int idx = tid; idx < 128 * 32; idx += 256) {
        int r = idx >> 5, kq = idx & 31;
        int row = row0 + r;
        float4 vM = {0.f, 0.f, 0.f, 0.f}, vH = {0.f, 0.f, 0.f, 0.f};
        if (row < n) {
            vM = *(const float4*)(mean + (size_t)row * DD + kq * 4);
            vH = *(const float4*)(h + (size_t)row * DD + kq * 4);
        }
        *(float4*)&sM[r * 132 + kq * 4] = vM;
        *(float4*)&sH[r * 132 + kq * 4] = vH;
    }
    // stage W tiles: 128 k x 16 float4 (64 cols)
    for (int idx = tid; idx < 128 * 16; idx += 256) {
        int k = idx >> 4, cq = idx & 15;
        *(float4*)&sWl[k * 64 + cq * 4] = *(const float4*)(wl + (size_t)k * DD + c0 + cq * 4);
        *(float4*)&sWr[k * 64 + cq * 4] = *(const float4*)(wr + (size_t)k * DD + c0 + cq * 4);
    }
    __syncthreads();

    int cg = tid & 7;    // col group: cols cg*4..+3 and 32+cg*4..+3
    int rg = tid >> 3;   // row group: rows rg*4..+3

    float acc[4][8];
    #pragma unroll
    for (int i2 = 0; i2 < 4; i2++)
        #pragma unroll
        for (int j = 0; j < 8; j++) acc[i2][j] = 0.f;

    #pragma unroll 2
    for (int k = 0; k < 128; k += 4) {
        float am[4][4], ah[4][4];
        #pragma unroll
        for (int i2 = 0; i2 < 4; i2++) {
            *(float4*)am[i2] = *(float4*)&sM[(rg * 4 + i2) * 132 + k];
            *(float4*)ah[i2] = *(float4*)&sH[(rg * 4 + i2) * 132 + k];
        }
        #pragma unroll
        for (int ks = 0; ks < 4; ks++) {
            float wlv[8], wrv[8];
            *(float4*)&wlv[0] = *(float4*)&sWl[(k + ks) * 64 + cg * 4];
            *(float4*)&wlv[4] = *(float4*)&sWl[(k + ks) * 64 + 32 + cg * 4];
            *(float4*)&wrv[0] = *(float4*)&sWr[(k + ks) * 64 + cg * 4];
            *(float4*)&wrv[4] = *(float4*)&sWr[(k + ks) * 64 + 32 + cg * 4];
            #pragma unroll
            for (int i2 = 0; i2 < 4; i2++) {
                float a1 = am[i2][ks], a2 = ah[i2][ks];
                #pragma unroll
                for (int j = 0; j < 8; j++)
                    acc[i2][j] = fmaf(a1, wlv[j], fmaf(a2, wrv[j], acc[i2][j]));
            }
        }
    }

    // epilogue: + bias, optional relu, vectorized store
    float bv[8];
    *(float4*)&bv[0] = *(const float4*)(bias + c0 + cg * 4);
    *(float4*)&bv[4] = *(const float4*)(bias + c0 + 32 + cg * 4);
    #pragma unroll
    for (int i2 = 0; i2 < 4; i2++) {
        int row = row0 + rg * 4 + i2;
        if (row < n) {
            float o[8];
            #pragma unroll
            for (int j = 0; j < 8; j++) {
                float v = acc[i2][j] + bv[j];
                if (RELU) v = fmaxf(v, 0.f);
                o[j] = v;
            }
            *(float4*)(out + (size_t)row * DD + c0 + cg * 4) = *(float4*)&o[0];
            *(float4*)(out + (size_t)row * DD + c0 + 32 + cg * 4) = *(float4*)&o[4];
        }
    }
}

// ---------------- launch ----------------
extern "C" void kernel_launch(void* const* d_in, const int* in_sizes, int n_in,
                              void* d_out, int out_size) {
    const float* x   = (const float*)d_in[0];
    const int*   ei  = (const int*)d_in[1];     // int32 edge_index (2, E)
    const float* wl0 = (const float*)d_in[2];
    const float* wr0 = (const float*)d_in[3];
    const float* b0  = (const float*)d_in[4];
    const float* wl1 = (const float*)d_in[5];
    const float* wr1 = (const float*)d_in[6];
    const float* b1  = (const float*)d_in[7];
    const float* wl2 = (const float*)d_in[8];
    const float* wr2 = (const float*)d_in[9];
    const float* b2  = (const float*)d_in[10];
    float* out = (float*)d_out;

    int n = in_sizes[0] / DD;
    int E = in_sizes[1] / 2;

    float *mean_p, *ha_p, *hb_p;
    cudaGetSymbolAddress((void**)&mean_p, g_mean);
    cudaGetSymbolAddress((void**)&ha_p, g_ha);
    cudaGetSymbolAddress((void**)&hb_p, g_hb);

    cudaFuncSetAttribute((const void*)combine_kernel<true>,
                         cudaFuncAttributeMaxDynamicSharedMemorySize, SMEM_BYTES);
    cudaFuncSetAttribute((const void*)combine_kernel<false>,
                         cudaFuncAttributeMaxDynamicSharedMemorySize, SMEM_BYTES);

    // CSR build (edges are layer-invariant; do once)
    zero_counts<<<(n + 255) / 256, 256>>>(n);
    count_deg<<<(E + 255) / 256, 256>>>(ei, E);
    scan_kernel<<<1, 1024>>>(n);
    invdeg_kernel<<<(n + 255) / 256, 256>>>(n);
    fill_csr<<<(E + 255) / 256, 256>>>(ei, E);

    dim3 cgrid((n + 127) / 128, 2);
    int aggB = (n + 7) / 8;  // one warp per node, 8 warps per block

    // layer 0: x -> ha (relu)
    aggregate_kernel<<<aggB, 256>>>(x, n);
    combine_kernel<true><<<cgrid, 256, SMEM_BYTES>>>(mean_p, x, wl0, wr0, b0, ha_p, n);

    // layer 1: ha -> hb (relu)
    aggregate_kernel<<<aggB, 256>>>(ha_p, n);
    combine_kernel<true><<<cgrid, 256, SMEM_BYTES>>>(mean_p, ha_p, wl1, wr1, b1, hb_p, n);

    // layer 2: hb -> out (no relu)
    aggregate_kernel<<<aggB, 256>>>(hb_p, n);
    combine_kernel<false><<<cgrid, 256, SMEM_BYTES>>>(mean_p, hb_p, wl2, wr2, b2, out, n);
}

// round 5
// speedup vs baseline: 1.8296x; 1.8296x over previous
#include <cuda_runtime.h>
#include <cuda_bf16.h>
#include <cstdint>

#define DD 128
#define MAXN 50000
#define MAXE 800000

// ---------------- device scratch ----------------
__device__ float g_mean[(size_t)MAXN * DD];
__device__ float g_ha[(size_t)MAXN * DD];
__device__ float g_hb[(size_t)MAXN * DD];
__device__ float g_invdeg[MAXN];
__device__ int   g_degi[MAXN];
__device__ int   g_rowstart[MAXN + 1];
__device__ int   g_cursor[MAXN];
__device__ int   g_csr[MAXE];
// pre-split, transposed weights: [mat][n*128 + k], mat = 2*layer + {0:Wl,1:Wr}
__device__ __nv_bfloat16 g_wthi[6 * 128 * 128];
__device__ __nv_bfloat16 g_wtlo[6 * 128 * 128];

// ---------------- helpers ----------------
static __device__ __forceinline__ uint32_t smem_u32(const void* p) {
    uint32_t a;
    asm("{ .reg .u64 t; cvta.to.shared.u64 t, %1; cvt.u32.u64 %0, t; }" : "=r"(a) : "l"(p));
    return a;
}
static __device__ __forceinline__ void ldsm_x4(uint32_t* r, uint32_t addr) {
    asm volatile("ldmatrix.sync.aligned.m8n8.x4.shared.b16 {%0,%1,%2,%3}, [%4];"
                 : "=r"(r[0]), "=r"(r[1]), "=r"(r[2]), "=r"(r[3]) : "r"(addr));
}
static __device__ __forceinline__ void mma16816(float* c, const uint32_t* a, const uint32_t* b) {
    asm volatile("mma.sync.aligned.m16n8k16.row.col.f32.bf16.bf16.f32 "
                 "{%0,%1,%2,%3}, {%4,%5,%6,%7}, {%8,%9}, {%0,%1,%2,%3};"
                 : "+f"(c[0]), "+f"(c[1]), "+f"(c[2]), "+f"(c[3])
                 : "r"(a[0]), "r"(a[1]), "r"(a[2]), "r"(a[3]), "r"(b[0]), "r"(b[1]));
}

// ---------------- CSR construction ----------------
__global__ void zero_counts(int n) {
    int i = blockIdx.x * blockDim.x + threadIdx.x;
    if (i < n) { g_degi[i] = 0; g_cursor[i] = 0; }
}
__global__ void count_deg(const int* __restrict__ ei, int E) {
    int e = blockIdx.x * blockDim.x + threadIdx.x;
    if (e < E) atomicAdd(&g_degi[ei[E + e]], 1);
}
__global__ void scan_kernel(int n) {
    __shared__ int warp_sums[32];
    __shared__ int s_carry;
    int t = threadIdx.x, lane = t & 31, w = t >> 5;
    if (t == 0) { g_rowstart[0] = 0; s_carry = 0; }
    __syncthreads();
    for (int base = 0; base < n; base += 1024) {
        int i = base + t;
        int x = (i < n) ? g_degi[i] : 0;
        #pragma unroll
        for (int off = 1; off < 32; off <<= 1) {
            int y = __shfl_up_sync(0xFFFFFFFFu, x, off);
            if (lane >= off) x += y;
        }
        if (lane == 31) warp_sums[w] = x;
        __syncthreads();
        if (w == 0) {
            int s = warp_sums[lane];
            #pragma unroll
            for (int off = 1; off < 32; off <<= 1) {
                int y = __shfl_up_sync(0xFFFFFFFFu, s, off);
                if (lane >= off) s += y;
            }
            warp_sums[lane] = s;
        }
        __syncthreads();
        int incl = x + (w > 0 ? warp_sums[w - 1] : 0) + s_carry;
        if (i < n) g_rowstart[i + 1] = incl;
        __syncthreads();
        if (t == 1023) s_carry = incl;
        __syncthreads();
    }
}
__global__ void invdeg_kernel(int n) {
    int i = blockIdx.x * blockDim.x + threadIdx.x;
    if (i < n) {
        int dg = g_degi[i];
        g_invdeg[i] = 1.0f / (float)(dg > 0 ? dg : 1);
    }
}
__global__ void fill_csr(const int* __restrict__ ei, int E) {
    int e = blockIdx.x * blockDim.x + threadIdx.x;
    if (e < E) {
        int s = ei[e];
        int d = ei[E + e];
        int p = atomicAdd(&g_cursor[d], 1);
        g_csr[g_rowstart[d] + p] = s;
    }
}

// ---------------- weight pre-split (transpose + bf16 hi/lo) ----------------
__global__ void wsplit_kernel(const float* w0, const float* w1, const float* w2,
                              const float* w3, const float* w4, const float* w5) {
    int id = blockIdx.x * blockDim.x + threadIdx.x;
    if (id >= 6 * 128 * 128) return;
    int mat = id >> 14, rem = id & 16383;
    int nn = rem >> 7, kk = rem & 127;
    const float* w;
    switch (mat) {
        case 0: w = w0; break; case 1: w = w1; break; case 2: w = w2; break;
        case 3: w = w3; break; case 4: w = w4; break; default: w = w5; break;
    }
    float v = w[kk * 128 + nn];           // transpose: wt[n][k] = w[k][n]
    __nv_bfloat16 hi = __float2bfloat16(v);
    g_wthi[id] = hi;
    g_wtlo[id] = __float2bfloat16(v - __bfloat162float(hi));
}

// ---------------- aggregation: warp per node, gather-only ----------------
__global__ void aggregate_kernel(const float* __restrict__ hin, int n) {
    int gw = (blockIdx.x * blockDim.x + threadIdx.x) >> 5;
    int lane = threadIdx.x & 31;
    if (gw >= n) return;
    int s0 = g_rowstart[gw], s1 = g_rowstart[gw + 1];
    float ax = 0.f, ay = 0.f, az = 0.f, aw = 0.f;
    int i = s0;
    for (; i + 4 <= s1; i += 4) {
        int e0 = g_csr[i], e1 = g_csr[i + 1], e2 = g_csr[i + 2], e3 = g_csr[i + 3];
        float4 v0 = *(const float4*)(hin + (size_t)e0 * DD + lane * 4);
        float4 v1 = *(const float4*)(hin + (size_t)e1 * DD + lane * 4);
        float4 v2 = *(const float4*)(hin + (size_t)e2 * DD + lane * 4);
        float4 v3 = *(const float4*)(hin + (size_t)e3 * DD + lane * 4);
        ax += v0.x + v1.x + v2.x + v3.x;
        ay += v0.y + v1.y + v2.y + v3.y;
        az += v0.z + v1.z + v2.z + v3.z;
        aw += v0.w + v1.w + v2.w + v3.w;
    }
    for (; i < s1; i++) {
        int e0 = g_csr[i];
        float4 v = *(const float4*)(hin + (size_t)e0 * DD + lane * 4);
        ax += v.x; ay += v.y; az += v.z; aw += v.w;
    }
    float inv = g_invdeg[gw];
    float4 r;
    r.x = ax * inv; r.y = ay * inv; r.z = az * inv; r.w = aw * inv;
    *(float4*)(g_mean + (size_t)gw * DD + lane * 4) = r;
}

// ---------------- mma.sync combine: out = mean @ Wl + h @ Wr + b (+ReLU) ----------------
// 3-term bf16 split: A@B ~= Ahi@Bhi + Ahi@Blo + Alo@Bhi  (residual ~2^-16)
// Dual GEMM = K-concat: chunk0 = (mean, Wl), chunk1 = (h, Wr), accumulators persist.
// CTA 128x128, 8 warps (4 row x 2 col), warp tile 32x64. Smem rows padded to 272B.
// B fragment note: weights staged [n][k]; mma m16n8k16 B wants lane l ->
// B[k=(l&3)*2+{0,1}][n=l>>2], which a NON-trans ldmatrix over n-rows delivers.
#define KPAD_B 272                       // 136 bf16 per row = 17 x 16B -> ldmatrix conflict-free
#define A_HI 0
#define A_LO (128 * KPAD_B)
#define B_HI (2 * 128 * KPAD_B)
#define B_LO (3 * 128 * KPAD_B)
#define CMB_SMEM (4 * 128 * KPAD_B)      // 139,264 bytes

template <bool RELU>
__global__ __launch_bounds__(256, 1) void combine_mma(
    const float* __restrict__ mean, const float* __restrict__ h,
    const __nv_bfloat16* __restrict__ wthi, const __nv_bfloat16* __restrict__ wtlo,
    const float* __restrict__ bias, float* __restrict__ out, int n)
{
    extern __shared__ char smem[];
    uint32_t sb = smem_u32(smem);
    int tid = threadIdx.x, wid = tid >> 5, lane = tid & 31;
    int row0 = blockIdx.x * 128;
    int wR = wid >> 1, wC = wid & 1;

    float acc[2][8][4];
    #pragma unroll
    for (int mi = 0; mi < 2; mi++)
        #pragma unroll
        for (int nj = 0; nj < 8; nj++)
            #pragma unroll
            for (int q = 0; q < 4; q++) acc[mi][nj][q] = 0.f;

    // ldmatrix lane-pointer components (fixed per thread)
    int a_row  = wR * 32 + (lane & 15);
    int a_koff = (lane >> 4) * 8;
    // B x4 (non-trans): lanes 0-7 -> n-grp0/k0, 8-15 -> n-grp0/k8, 16-23 -> n-grp1/k0, 24-31 -> n-grp1/k8
    int b_nrow = wC * 64 + (lane & 7) + ((lane >> 4) << 3);
    int b_koff = ((lane >> 3) & 1) * 8;

    #pragma unroll
    for (int chunk = 0; chunk < 2; chunk++) {
        // ---- stage A chunk: fp32 -> bf16 hi/lo ----
        const float* src = chunk ? h : mean;
        for (int idx = tid; idx < 4096; idx += 256) {
            int r = idx >> 5, kq = idx & 31;
            int row = row0 + r;
            float4 v = {0.f, 0.f, 0.f, 0.f};
            if (row < n) v = *(const float4*)(src + (size_t)row * DD + kq * 4);
            __nv_bfloat16 hx = __float2bfloat16(v.x), hy = __float2bfloat16(v.y);
            __nv_bfloat16 hz = __float2bfloat16(v.z), hw = __float2bfloat16(v.w);
            __nv_bfloat162 h01, h23, l01, l23;
            h01.x = hx; h01.y = hy; h23.x = hz; h23.y = hw;
            l01.x = __float2bfloat16(v.x - __bfloat162float(hx));
            l01.y = __float2bfloat16(v.y - __bfloat162float(hy));
            l23.x = __float2bfloat16(v.z - __bfloat162float(hz));
            l23.y = __float2bfloat16(v.w - __bfloat162float(hw));
            uint2 hp, lp;
            hp.x = *(uint32_t*)&h01; hp.y = *(uint32_t*)&h23;
            lp.x = *(uint32_t*)&l01; lp.y = *(uint32_t*)&l23;
            *(uint2*)(smem + A_HI + r * KPAD_B + kq * 8) = hp;
            *(uint2*)(smem + A_LO + r * KPAD_B + kq * 8) = lp;
        }
        // ---- stage B chunk: pre-split transposed weights [n][k] ----
        const __nv_bfloat16* bh = wthi + chunk * 16384;
        const __nv_bfloat16* bl = wtlo + chunk * 16384;
        for (int idx = tid; idx < 2048; idx += 256) {
            int nr = idx >> 4, kg = idx & 15;
            *(uint4*)(smem + B_HI + nr * KPAD_B + kg * 16) = *(const uint4*)(bh + nr * 128 + kg * 8);
            *(uint4*)(smem + B_LO + nr * KPAD_B + kg * 16) = *(const uint4*)(bl + nr * 128 + kg * 8);
        }
        __syncthreads();

        #pragma unroll
        for (int ks = 0; ks < 8; ks++) {
            int k0 = ks * 16;
            uint32_t aF[2][2][4];   // [plane][mi]
            #pragma unroll
            for (int p = 0; p < 2; p++)
                #pragma unroll
                for (int mi = 0; mi < 2; mi++)
                    ldsm_x4(aF[p][mi],
                            sb + (p ? A_LO : A_HI) + (a_row + mi * 16) * KPAD_B + (k0 + a_koff) * 2);
            uint32_t bF[2][4][4];   // [plane][n16 group]
            #pragma unroll
            for (int p = 0; p < 2; p++)
                #pragma unroll
                for (int gj = 0; gj < 4; gj++)
                    ldsm_x4(bF[p][gj],
                            sb + (p ? B_LO : B_HI) + (b_nrow + gj * 16) * KPAD_B + (k0 + b_koff) * 2);
            #pragma unroll
            for (int mi = 0; mi < 2; mi++)
                #pragma unroll
                for (int nj = 0; nj < 8; nj++) {
                    int gj = nj >> 1, s = (nj & 1) * 2;
                    mma16816(acc[mi][nj], aF[0][mi], &bF[0][gj][s]);  // hi*hi
                    mma16816(acc[mi][nj], aF[0][mi], &bF[1][gj][s]);  // hi*lo
                    mma16816(acc[mi][nj], aF[1][mi], &bF[0][gj][s]);  // lo*hi
                }
        }
        __syncthreads();
    }

    // ---- epilogue: bias (+ReLU), direct stores ----
    #pragma unroll
    for (int mi = 0; mi < 2; mi++) {
        int r0a = row0 + wR * 32 + mi * 16 + (lane >> 2);
        #pragma unroll
        for (int nj = 0; nj < 8; nj++) {
            int col = wC * 64 + nj * 8 + (lane & 3) * 2;
            float2 bb = *(const float2*)(bias + col);
            float2 v0, v1;
            v0.x = acc[mi][nj][0] + bb.x; v0.y = acc[mi][nj][1] + bb.y;
            v1.x = acc[mi][nj][2] + bb.x; v1.y = acc[mi][nj][3] + bb.y;
            if (RELU) {
                v0.x = fmaxf(v0.x, 0.f); v0.y = fmaxf(v0.y, 0.f);
                v1.x = fmaxf(v1.x, 0.f); v1.y = fmaxf(v1.y, 0.f);
            }
            if (r0a < n)     *(float2*)(out + (size_t)r0a * DD + col) = v0;
            if (r0a + 8 < n) *(float2*)(out + (size_t)(r0a + 8) * DD + col) = v1;
        }
    }
}

// ---------------- launch ----------------
extern "C" void kernel_launch(void* const* d_in, const int* in_sizes, int n_in,
                              void* d_out, int out_size) {
    const float* x   = (const float*)d_in[0];
    const int*   ei  = (const int*)d_in[1];
    const float* wl0 = (const float*)d_in[2];
    const float* wr0 = (const float*)d_in[3];
    const float* b0  = (const float*)d_in[4];
    const float* wl1 = (const float*)d_in[5];
    const float* wr1 = (const float*)d_in[6];
    const float* b1  = (const float*)d_in[7];
    const float* wl2 = (const float*)d_in[8];
    const float* wr2 = (const float*)d_in[9];
    const float* b2  = (const float*)d_in[10];
    float* out = (float*)d_out;

    int n = in_sizes[0] / DD;
    int E = in_sizes[1] / 2;

    float *mean_p, *ha_p, *hb_p;
    __nv_bfloat16 *wthi_p, *wtlo_p;
    cudaGetSymbolAddress((void**)&mean_p, g_mean);
    cudaGetSymbolAddress((void**)&ha_p, g_ha);
    cudaGetSymbolAddress((void**)&hb_p, g_hb);
    cudaGetSymbolAddress((void**)&wthi_p, g_wthi);
    cudaGetSymbolAddress((void**)&wtlo_p, g_wtlo);

    cudaFuncSetAttribute((const void*)combine_mma<true>,
                         cudaFuncAttributeMaxDynamicSharedMemorySize, CMB_SMEM);
    cudaFuncSetAttribute((const void*)combine_mma<false>,
                         cudaFuncAttributeMaxDynamicSharedMemorySize, CMB_SMEM);

    // prep: CSR + weight split (edges/weights layer-invariant)
    zero_counts<<<(n + 255) / 256, 256>>>(n);
    count_deg<<<(E + 255) / 256, 256>>>(ei, E);
    scan_kernel<<<1, 1024>>>(n);
    invdeg_kernel<<<(n + 255) / 256, 256>>>(n);
    fill_csr<<<(E + 255) / 256, 256>>>(ei, E);
    wsplit_kernel<<<(6 * 128 * 128 + 255) / 256, 256>>>(wl0, wr0, wl1, wr1, wl2, wr2);

    int aggB = (n + 7) / 8;
    int cmbB = (n + 127) / 128;

    // layer 0: x -> ha (relu)
    aggregate_kernel<<<aggB, 256>>>(x, n);
    combine_mma<true><<<cmbB, 256, CMB_SMEM>>>(mean_p, x, wthi_p, wtlo_p, b0, ha_p, n);

    // layer 1: ha -> hb (relu)
    aggregate_kernel<<<aggB, 256>>>(ha_p, n);
    combine_mma<true><<<cmbB, 256, CMB_SMEM>>>(mean_p, ha_p, wthi_p + 2 * 16384, wtlo_p + 2 * 16384, b1, hb_p, n);

    // layer 2: hb -> out (no relu)
    aggregate_kernel<<<aggB, 256>>>(hb_p, n);
    combine_mma<false><<<cmbB, 256, CMB_SMEM>>>(mean_p, hb_p, wthi_p + 4 * 16384, wtlo_p + 4 * 16384, b2, out, n);
}